// round 2
// baseline (speedup 1.0000x reference)
#include <cuda_runtime.h>

// WaveletMask: fused Haar fwd -> mosaic weight multiply -> Haar inv.
// H=128, HB=64. One thread per TWO adjacent 2x2 blocks (float4 path).
// 2048 threads = 64 blocks x 32 threads (1 warp/SM on 64 SMs).
// Per thread: 2x LDG.128 (x), 4x LDG.64 (w), 2x STG.128 (out). All independent.

#define H 128
#define HB 64

__global__ void __launch_bounds__(32, 1) wavelet_mask_kernel(
    const float* __restrict__ x,
    const float* __restrict__ w,
    float* __restrict__ out)
{
    const int t = blockIdx.x * 32 + threadIdx.x;   // 0..2047
    const int i = t >> 5;                          // block row 0..63
    const int q = t & 31;                          // quad-column 0..31 (covers block cols 2q, 2q+1)

    const int xoff = (2 * i) * H + 4 * q;
    // Two adjacent 2x2 input blocks, vectorized
    const float4 top = *reinterpret_cast<const float4*>(x + xoff);
    const float4 bot = *reinterpret_cast<const float4*>(x + xoff + H);

    // Mosaic weights for block cols 2q and 2q+1 (contiguous per quadrant)
    const float2 wll = *reinterpret_cast<const float2*>(w + i * H + 2 * q);
    const float2 wlh = *reinterpret_cast<const float2*>(w + i * H + 2 * q + HB);
    const float2 whl = *reinterpret_cast<const float2*>(w + (i + HB) * H + 2 * q);
    const float2 whh = *reinterpret_cast<const float2*>(w + (i + HB) * H + 2 * q + HB);

    float4 otop, obot;

    // ---- block 0: (top.x, top.y, bot.x, bot.y) ----
    {
        const float apb = top.x + top.y, amb = top.x - top.y;
        const float cpd = bot.x + bot.y, cmd = bot.x - bot.y;
        const float ll = (apb + cpd) * 0.5f * wll.x;
        const float lh = (apb - cpd) * 0.5f * wlh.x;
        const float hl = (amb + cmd) * 0.5f * whl.x;
        const float hh = (amb - cmd) * 0.5f * whh.x;
        const float lp = ll + lh, lm = ll - lh;
        const float hp = hl + hh, hm = hl - hh;
        otop.x = (lp + hp) * 0.5f;
        otop.y = (lp - hp) * 0.5f;
        obot.x = (lm + hm) * 0.5f;
        obot.y = (lm - hm) * 0.5f;
    }
    // ---- block 1: (top.z, top.w, bot.z, bot.w) ----
    {
        const float apb = top.z + top.w, amb = top.z - top.w;
        const float cpd = bot.z + bot.w, cmd = bot.z - bot.w;
        const float ll = (apb + cpd) * 0.5f * wll.y;
        const float lh = (apb - cpd) * 0.5f * wlh.y;
        const float hl = (amb + cmd) * 0.5f * whl.y;
        const float hh = (amb - cmd) * 0.5f * whh.y;
        const float lp = ll + lh, lm = ll - lh;
        const float hp = hl + hh, hm = hl - hh;
        otop.z = (lp + hp) * 0.5f;
        otop.w = (lp - hp) * 0.5f;
        obot.z = (lm + hm) * 0.5f;
        obot.w = (lm - hm) * 0.5f;
    }

    *reinterpret_cast<float4*>(out + xoff)     = otop;
    *reinterpret_cast<float4*>(out + xoff + H) = obot;
}

extern "C" void kernel_launch(void* const* d_in, const int* in_sizes, int n_in,
                              void* d_out, int out_size)
{
    const float* x = (const float*)d_in[0];
    const float* w = (const float*)d_in[1];
    float* out = (float*)d_out;
    wavelet_mask_kernel<<<64, 32>>>(x, w, out);
}

// round 4
// speedup vs baseline: 1.1319x; 1.1319x over previous
#include <cuda_runtime.h>

// WaveletMask: fused Haar fwd -> mosaic weight multiply -> Haar inv.
// H=128, HB=64. One thread per TWO adjacent 2x2 blocks (float4 path).
// 2048 threads = 16 blocks x 128 threads (4 warps/block).
// Per thread: 2x LDG.128 (x), 4x LDG.64 (w), 2x STG.128 (out). All independent.

#define H 128
#define HB 64

__global__ void __launch_bounds__(128, 1) wavelet_mask_kernel(
    const float* __restrict__ x,
    const float* __restrict__ w,
    float* __restrict__ out)
{
    const int t = blockIdx.x * 128 + threadIdx.x;  // 0..2047
    const int i = t >> 5;                          // block row 0..63
    const int q = t & 31;                          // quad-column 0..31 (block cols 2q, 2q+1)

    const int xoff = (2 * i) * H + 4 * q;
    // Two adjacent 2x2 input blocks, vectorized
    const float4 top = *reinterpret_cast<const float4*>(x + xoff);
    const float4 bot = *reinterpret_cast<const float4*>(x + xoff + H);

    // Mosaic weights for block cols 2q and 2q+1 (contiguous per quadrant)
    const float2 wll = *reinterpret_cast<const float2*>(w + i * H + 2 * q);
    const float2 wlh = *reinterpret_cast<const float2*>(w + i * H + 2 * q + HB);
    const float2 whl = *reinterpret_cast<const float2*>(w + (i + HB) * H + 2 * q);
    const float2 whh = *reinterpret_cast<const float2*>(w + (i + HB) * H + 2 * q + HB);

    float4 otop, obot;

    // ---- block 0: (top.x, top.y, bot.x, bot.y) ----
    {
        const float apb = top.x + top.y, amb = top.x - top.y;
        const float cpd = bot.x + bot.y, cmd = bot.x - bot.y;
        const float ll = (apb + cpd) * 0.5f * wll.x;
        const float lh = (apb - cpd) * 0.5f * wlh.x;
        const float hl = (amb + cmd) * 0.5f * whl.x;
        const float hh = (amb - cmd) * 0.5f * whh.x;
        const float lp = ll + lh, lm = ll - lh;
        const float hp = hl + hh, hm = hl - hh;
        otop.x = (lp + hp) * 0.5f;
        otop.y = (lp - hp) * 0.5f;
        obot.x = (lm + hm) * 0.5f;
        obot.y = (lm - hm) * 0.5f;
    }
    // ---- block 1: (top.z, top.w, bot.z, bot.w) ----
    {
        const float apb = top.z + top.w, amb = top.z - top.w;
        const float cpd = bot.z + bot.w, cmd = bot.z - bot.w;
        const float ll = (apb + cpd) * 0.5f * wll.y;
        const float lh = (apb - cpd) * 0.5f * wlh.y;
        const float hl = (amb + cmd) * 0.5f * whl.y;
        const float hh = (amb - cmd) * 0.5f * whh.y;
        const float lp = ll + lh, lm = ll - lh;
        const float hp = hl + hh, hm = hl - hh;
        otop.z = (lp + hp) * 0.5f;
        otop.w = (lp - hp) * 0.5f;
        obot.z = (lm + hm) * 0.5f;
        obot.w = (lm - hm) * 0.5f;
    }

    *reinterpret_cast<float4*>(out + xoff)     = otop;
    *reinterpret_cast<float4*>(out + xoff + H) = obot;
}

extern "C" void kernel_launch(void* const* d_in, const int* in_sizes, int n_in,
                              void* d_out, int out_size)
{
    const float* x = (const float*)d_in[0];
    const float* w = (const float*)d_in[1];
    float* out = (float*)d_out;
    wavelet_mask_kernel<<<16, 128>>>(x, w, out);
}